// round 2
// baseline (speedup 1.0000x reference)
#include <cuda_runtime.h>
#include <math.h>

#define Bk   128
#define Hk   512
#define Tk   1024
#define INk  8
#define OUTk 2

#define JB   8
#define BBL  16
#define HJ   64      // H / JB
#define BC   8       // B / BBL
#define NCTA 128     // JB * BBL
#define NTHR 256
#define STEPS (Tk - 1)

// ---------------- device globals (no allocations allowed) ----------
__device__ float4 g_h[2][Bk][Hk / 4];          // hidden-state ping-pong
__device__ unsigned g_count;                   // barrier arrivals (returns to 0)
__device__ volatile unsigned g_epoch;          // barrier release epoch

// ---------------- shared memory layout ----------------
struct __align__(16) Smem {
    float Wt[Hk][HJ];        // W_rec slice transposed: Wt[k][j_local]  128 KB
    float hbuf[BC][Hk];      // staged h_pre                              16 KB
    float red[8][BC][HJ];    // per-warp K partials                       16 KB
    float hist[BC][HJ][8];   // 8-step h history                          16 KB
    float Win[HJ][INk];
    float bias[HJ];
    float Wk[OUTk][Hk];
    float bkey[OUTk];
    float x[BC][INk];
    float key0[BC];
    float kred[16][16];
};

__device__ __forceinline__ void grid_barrier() {
    __syncthreads();
    if (threadIdx.x == 0) {
        __threadfence();
        unsigned e = g_epoch;
        if (atomicAdd(&g_count, 1u) == NCTA - 1u) {
            atomicExch(&g_count, 0u);
            __threadfence();
            g_epoch = e + 1u;
        } else {
            while (g_epoch == e) { }
            __threadfence();
        }
    }
    __syncthreads();
}

__global__ void __launch_bounds__(NTHR, 1)
rnn_persistent_kernel(const float* __restrict__ inputs,   // [B][IN][T]
                      const float* __restrict__ W_in,     // [H][IN]
                      const float* __restrict__ b_in,
                      const float* __restrict__ W_rec,    // [H][H]
                      const float* __restrict__ b_rec,
                      const float* __restrict__ W_key,    // [OUT][H]
                      const float* __restrict__ b_key,
                      float* __restrict__ out)
{
    extern __shared__ char smraw[];
    Smem& s = *reinterpret_cast<Smem*>(smraw);

    const int tid = threadIdx.x;
    const int cta = blockIdx.x;
    const int jb  = cta % JB;
    const int bb  = cta / JB;
    const int jg0 = jb * HJ;
    const int bg0 = bb * BC;
    const bool keyCTA = (jb == 0);

    float* keysOut = out;                                            // [B][2][T]
    float* prsOut  = out + (size_t)Bk * 2 * Tk;                      // [B][4][T]
    float* hsOut   = out + (size_t)Bk * 2 * Tk + (size_t)Bk * 4 * Tk;// [B][H][T]

    // ---------------- one-time init ----------------
    for (int idx = tid; idx < HJ * Hk; idx += NTHR) {
        int j = idx / Hk, k = idx % Hk;
        s.Wt[k][j] = W_rec[(size_t)(jg0 + j) * Hk + k];
    }
    for (int idx = tid; idx < HJ * INk; idx += NTHR) {
        int j = idx / INk, i = idx % INk;
        s.Win[j][i] = W_in[(jg0 + j) * INk + i];
    }
    for (int j = tid; j < HJ; j += NTHR)
        s.bias[j] = b_in[jg0 + j] + b_rec[jg0 + j];
    if (keyCTA) {
        for (int idx = tid; idx < OUTk * Hk; idx += NTHR)
            s.Wk[idx / Hk][idx % Hk] = W_key[idx];
        if (tid < OUTk) s.bkey[tid] = b_key[tid];
        if (tid < BC * 2) {   // zero keys column 0
            int b = tid >> 1, o = tid & 1;
            keysOut[(size_t)(bg0 + b) * 2 * Tk + (size_t)o * Tk + 0] = 0.f;
        }
        if (tid < BC * 4) {   // zero prs column 0
            int b = tid >> 2, c = tid & 3;
            prsOut[(size_t)(bg0 + b) * 4 * Tk + (size_t)c * Tk + 0] = 0.f;
        }
    }
    // h_{-1} = 0 (must redo every launch; graph replays)
    for (int idx = tid; idx < BC * HJ; idx += NTHR) {
        int b = idx / HJ, k = idx % HJ;
        reinterpret_cast<float*>(&g_h[0][bg0 + b][0])[jg0 + k] = 0.f;
    }
    // hist slot 0 = hs column 0 = zeros
    for (int idx = tid; idx < BC * HJ; idx += NTHR) {
        int b = idx / HJ, j = idx % HJ;
        s.hist[b][j][0] = 0.f;
    }
    __syncthreads();
    grid_barrier();

    // matvec mapping: warp owns 64-wide K slice; lane -> 4x4 (b x j) tile
    const int w     = tid >> 5;
    const int lane  = tid & 31;
    const int jgrp  = lane & 15;           // j0 = 4*jgrp
    const int b0    = (lane >> 4) * 4;     // 0 or 4
    const int kbase = w * 64;

    // ---------------- time loop ----------------
    for (int st = 0; st < STEPS; ++st) {
        const int par = st & 1;

        // stage h_pre and this step's input column
        {
            const float4* src = &g_h[par][bg0][0];
            float4* dst = reinterpret_cast<float4*>(&s.hbuf[0][0]);
            #pragma unroll
            for (int l = 0; l < 4; ++l) dst[tid + NTHR * l] = src[tid + NTHR * l];
        }
        if (tid < BC * INk) {
            int b = tid >> 3, i = tid & 7;
            s.x[b][i] = inputs[(size_t)(bg0 + b) * INk * Tk + (size_t)i * Tk + (st + 1)];
        }
        __syncthreads();

        // ---- key/pr head (jb==0 CTAs), key one step behind ----
        if (keyCTA) {
            if (st >= 1) {
                int p  = tid >> 4;          // 0..15 = (b,o)
                int kg = tid & 15;
                int b = p >> 1, o = p & 1;
                float acc = 0.f;
                #pragma unroll
                for (int kk = 0; kk < 32; ++kk) {
                    int k = kg * 32 + kk;
                    acc = fmaf(s.hbuf[b][k], s.Wk[o][k], acc);
                }
                s.kred[p][kg] = acc;
                __syncthreads();
                if (tid < 16) {
                    int b2 = tid >> 1, o2 = tid & 1;
                    float z = s.bkey[o2];
                    #pragma unroll
                    for (int g = 0; g < 16; ++g) z += s.kred[tid][g];
                    float kv = 1.f / (1.f + expf(-z));
                    keysOut[(size_t)(bg0 + b2) * 2 * Tk + (size_t)o2 * Tk + st] = kv;
                    if (o2 == 0) s.key0[b2] = kv;
                }
                __syncthreads();
            }
            if (tid < BC * 4) {
                int b = tid >> 2, c = tid & 3;
                float kp = (st >= 1) ? s.key0[b] : 1.0f;
                float tm, arm;
                if (c < 2) { tm = s.x[b][6]; arm = s.x[b][c]; }
                else       { tm = s.x[b][7]; arm = s.x[b][c] * kp + s.x[b][c + 2] * (1.f - kp); }
                float d = (tm - arm) / (0.15f * arm);
                float v = (tm == 0.f) ? 0.f : d * d;
                prsOut[(size_t)(bg0 + b) * 4 * Tk + (size_t)c * Tk + (st + 1)] = v;
            }
        }

        // ---- recurrent matvec partials ----
        float a00=0,a01=0,a02=0,a03=0, a10=0,a11=0,a12=0,a13=0;
        float a20=0,a21=0,a22=0,a23=0, a30=0,a31=0,a32=0,a33=0;
        {
            const float4* h4 = reinterpret_cast<const float4*>(&s.hbuf[0][0]);
            const float*  wp = &s.Wt[kbase][jgrp * 4];
            const int kq0 = kbase >> 2;
            #pragma unroll 4
            for (int k4 = 0; k4 < 16; ++k4) {
                float hv0[4], hv1[4], hv2[4], hv3[4];
                *reinterpret_cast<float4*>(hv0) = h4[(b0 + 0) * 128 + kq0 + k4];
                *reinterpret_cast<float4*>(hv1) = h4[(b0 + 1) * 128 + kq0 + k4];
                *reinterpret_cast<float4*>(hv2) = h4[(b0 + 2) * 128 + kq0 + k4];
                *reinterpret_cast<float4*>(hv3) = h4[(b0 + 3) * 128 + kq0 + k4];
                #pragma unroll
                for (int kk = 0; kk < 4; ++kk) {
                    float4 wv = *reinterpret_cast<const float4*>(wp + (k4 * 4 + kk) * HJ);
                    a00 = fmaf(wv.x, hv0[kk], a00); a01 = fmaf(wv.y, hv0[kk], a01);
                    a02 = fmaf(wv.z, hv0[kk], a02); a03 = fmaf(wv.w, hv0[kk], a03);
                    a10 = fmaf(wv.x, hv1[kk], a10); a11 = fmaf(wv.y, hv1[kk], a11);
                    a12 = fmaf(wv.z, hv1[kk], a12); a13 = fmaf(wv.w, hv1[kk], a13);
                    a20 = fmaf(wv.x, hv2[kk], a20); a21 = fmaf(wv.y, hv2[kk], a21);
                    a22 = fmaf(wv.z, hv2[kk], a22); a23 = fmaf(wv.w, hv2[kk], a23);
                    a30 = fmaf(wv.x, hv3[kk], a30); a31 = fmaf(wv.y, hv3[kk], a31);
                    a32 = fmaf(wv.z, hv3[kk], a32); a33 = fmaf(wv.w, hv3[kk], a33);
                }
            }
        }
        *reinterpret_cast<float4*>(&s.red[w][b0 + 0][jgrp * 4]) = make_float4(a00, a01, a02, a03);
        *reinterpret_cast<float4*>(&s.red[w][b0 + 1][jgrp * 4]) = make_float4(a10, a11, a12, a13);
        *reinterpret_cast<float4*>(&s.red[w][b0 + 2][jgrp * 4]) = make_float4(a20, a21, a22, a23);
        *reinterpret_cast<float4*>(&s.red[w][b0 + 3][jgrp * 4]) = make_float4(a30, a31, a32, a33);
        __syncthreads();

        // ---- finalize: reduce partials + input term + bias, tanh ----
        #pragma unroll
        for (int l = 0; l < 2; ++l) {
            int o = tid + l * NTHR;
            int b = o >> 6, j = o & 63;
            float v = s.bias[j];
            #pragma unroll
            for (int ww = 0; ww < 8; ++ww) v += s.red[ww][b][j];
            #pragma unroll
            for (int i = 0; i < INk; ++i) v = fmaf(s.x[b][i], s.Win[j][i], v);
            float h = tanhf(v);
            reinterpret_cast<float*>(&g_h[par ^ 1][bg0 + b][0])[jg0 + j] = h;
            s.hist[b][j][(st + 1) & 7] = h;
        }

        // ---- flush 8-step history to hs ----
        if (((st + 1) & 7) == 7) {
            __syncthreads();
            const int base = st - 6;
            #pragma unroll
            for (int l = 0; l < 2; ++l) {
                int o = tid + l * NTHR;
                int b = o >> 6, j = o & 63;
                float4 lo = *reinterpret_cast<float4*>(&s.hist[b][j][0]);
                float4 hi = *reinterpret_cast<float4*>(&s.hist[b][j][4]);
                float* dst = &hsOut[(size_t)(bg0 + b) * Hk * Tk + (size_t)(jg0 + j) * Tk + base];
                *reinterpret_cast<float4*>(dst)     = lo;
                *reinterpret_cast<float4*>(dst + 4) = hi;
            }
        }

        grid_barrier();
    }

    // ---- final key column: key[T-2] from h[1022] (in g_h[1]) -> keys[:,:,1023] ----
    if (keyCTA) {
        {
            const float4* src = &g_h[1][bg0][0];
            float4* dst = reinterpret_cast<float4*>(&s.hbuf[0][0]);
            #pragma unroll
            for (int l = 0; l < 4; ++l) dst[tid + NTHR * l] = src[tid + NTHR * l];
        }
        __syncthreads();
        int p  = tid >> 4;
        int kg = tid & 15;
        int b = p >> 1, o = p & 1;
        float acc = 0.f;
        #pragma unroll
        for (int kk = 0; kk < 32; ++kk) {
            int k = kg * 32 + kk;
            acc = fmaf(s.hbuf[b][k], s.Wk[o][k], acc);
        }
        s.kred[p][kg] = acc;
        __syncthreads();
        if (tid < 16) {
            int b2 = tid >> 1, o2 = tid & 1;
            float z = s.bkey[o2];
            #pragma unroll
            for (int g = 0; g < 16; ++g) z += s.kred[tid][g];
            float kv = 1.f / (1.f + expf(-z));
            keysOut[(size_t)(bg0 + b2) * 2 * Tk + (size_t)o2 * Tk + (Tk - 1)] = kv;
        }
    }
}

extern "C" void kernel_launch(void* const* d_in, const int* in_sizes, int n_in,
                              void* d_out, int out_size) {
    const float* inputs = (const float*)d_in[0];
    const float* W_in   = (const float*)d_in[1];
    const float* b_in   = (const float*)d_in[2];
    const float* W_rec  = (const float*)d_in[3];
    const float* b_rec  = (const float*)d_in[4];
    const float* W_key  = (const float*)d_in[5];
    const float* b_key  = (const float*)d_in[6];
    float* out = (float*)d_out;

    static bool attr_set = false;
    if (!attr_set) {
        cudaFuncSetAttribute(rnn_persistent_kernel,
                             cudaFuncAttributeMaxDynamicSharedMemorySize,
                             (int)sizeof(Smem));
        attr_set = true;
    }
    rnn_persistent_kernel<<<NCTA, NTHR, sizeof(Smem)>>>(
        inputs, W_in, b_in, W_rec, b_rec, W_key, b_key, out);
}

// round 3
// speedup vs baseline: 1.1344x; 1.1344x over previous
#include <cuda_runtime.h>
#include <math.h>

#define Bk   128
#define Hk   512
#define Tk   1024
#define INk  8
#define OUTk 2

#define JB   8
#define BBL  16
#define HJ   64      // H / JB
#define BC   8       // B / BBL
#define NCTA 128     // JB * BBL
#define NTHR 256
#define STEPS (Tk - 1)

typedef unsigned long long ull;

// ---------------- device globals ----------------
// h ping-pong, sliced: g_h[par][bb][jb][b*64+j]
__device__ float g_h[2][BBL][JB][BC * HJ];
// per-slice ready flags (padded to 32B): g_flag[bb][jb][0] = latest step s such that h[s] slice is written
__device__ volatile int g_flag[BBL][JB][8];
// init-only global barrier
__device__ unsigned g_count;
__device__ volatile unsigned g_epoch;

// ---------------- shared memory ----------------
struct __align__(16) Smem {
    ull   wt2[Hk / 2][HJ];     // W_rec slice, k-pair packed: wt2[k2][j] = (W[j][2k2], W[j][2k2+1])  128 KB
    float hbuf[BC][Hk];        // staged h_pre (full H for this CTA's 8 batches)                      16 KB
    float red[8][BC][HJ];      // per-warp K partials                                                  16 KB
    float hist[BC][HJ][8];     // 8-step h history for coalesced hs stores                             16 KB
    float Win[HJ][INk];
    float bias[HJ];
    float Wk[OUTk][Hk];
    float bkey[OUTk];
    float x[2][BC][INk];       // double-buffered input column
    float key0[BC];
    float kred[16][16];
};

union F2U { ull u; float2 f; };

__device__ __forceinline__ void fma2(ull& d, ull a, ull b) {
    asm("fma.rn.f32x2 %0, %1, %2, %0;" : "+l"(d) : "l"(a), "l"(b));
}

__device__ __forceinline__ void init_grid_barrier() {
    __syncthreads();
    if (threadIdx.x == 0) {
        __threadfence();
        unsigned e = g_epoch;
        if (atomicAdd(&g_count, 1u) == NCTA - 1u) {
            atomicExch(&g_count, 0u);
            __threadfence();
            g_epoch = e + 1u;
        } else {
            while (g_epoch == e) { }
            __threadfence();
        }
    }
    __syncthreads();
}

__global__ void __launch_bounds__(NTHR, 1)
rnn_flag_kernel(const float* __restrict__ inputs,   // [B][IN][T]
                const float* __restrict__ W_in,     // [H][IN]
                const float* __restrict__ b_in,
                const float* __restrict__ W_rec,    // [H][H]
                const float* __restrict__ b_rec,
                const float* __restrict__ W_key,    // [OUT][H]
                const float* __restrict__ b_key,
                float* __restrict__ out)
{
    extern __shared__ char smraw[];
    Smem& s = *reinterpret_cast<Smem*>(smraw);

    const int tid = threadIdx.x;
    const int cta = blockIdx.x;
    const int jb  = cta % JB;
    const int bb  = cta / JB;
    const int jg0 = jb * HJ;
    const int bg0 = bb * BC;
    const bool keyCTA = (jb == 0);

    float* keysOut = out;                                             // [B][2][T]
    float* prsOut  = out + (size_t)Bk * 2 * Tk;                       // [B][4][T]
    float* hsOut   = out + (size_t)Bk * 2 * Tk + (size_t)Bk * 4 * Tk; // [B][H][T]

    // ---------------- one-time init ----------------
    {   // W_rec -> k-pair packed smem (coalesced global float2 reads)
        const float2* wr2 = reinterpret_cast<const float2*>(W_rec);
        for (int idx = tid; idx < HJ * (Hk / 2); idx += NTHR) {
            int j  = idx >> 8;           // 0..63
            int k2 = idx & 255;          // 0..255
            F2U u; u.f = wr2[(size_t)(jg0 + j) * (Hk / 2) + k2];
            s.wt2[k2][j] = u.u;
        }
    }
    for (int idx = tid; idx < HJ * INk; idx += NTHR) {
        int j = idx / INk, i = idx % INk;
        s.Win[j][i] = W_in[(jg0 + j) * INk + i];
    }
    for (int j = tid; j < HJ; j += NTHR)
        s.bias[j] = b_in[jg0 + j] + b_rec[jg0 + j];
    if (keyCTA) {
        for (int idx = tid; idx < OUTk * Hk; idx += NTHR)
            s.Wk[idx / Hk][idx % Hk] = W_key[idx];
        if (tid < OUTk) s.bkey[tid] = b_key[tid];
        if (tid < BC) s.key0[tid] = 1.0f;
        if (tid < BC * 2) {    // keys column 0 = 0
            int b = tid >> 1, o = tid & 1;
            keysOut[(size_t)(bg0 + b) * 2 * Tk + (size_t)o * Tk + 0] = 0.f;
        }
        if (tid < BC * 4) {    // prs column 0 = 0
            int b = tid >> 2, c = tid & 3;
            prsOut[(size_t)(bg0 + b) * 4 * Tk + (size_t)c * Tk + 0] = 0.f;
        }
    }
    // h[0] = 0 (own slice); reset own flag; hist slot 0 = 0
    for (int o = tid; o < BC * HJ; o += NTHR)
        g_h[0][bb][jb][o] = 0.f;
    if (tid == 0) g_flag[bb][jb][0] = 0;
    for (int o = tid; o < BC * HJ; o += NTHR) {
        int b = o >> 6, j = o & 63;
        s.hist[b][j][0] = 0.f;
    }
    __syncthreads();
    init_grid_barrier();   // all flags reset & h[0] visible before anyone polls

    const int w    = tid >> 5;
    const int lane = tid & 31;
    const int jgrp = lane & 15;          // j0 = 4*jgrp
    const int b0   = (lane >> 4) * 4;    // 0 or 4

    const ulonglong2* w2row = reinterpret_cast<const ulonglong2*>(&s.wt2[0][0]); // [k2*32 + j/2]
    const ulonglong2* h2    = reinterpret_cast<const ulonglong2*>(&s.hbuf[0][0]);// [b*128 + k/4]

    // ================ time loop ================
    for (int st = 0; st < STEPS; ++st) {
        const int par = st & 1;
        const int xp  = st & 1;

        // stage input column st+1 (consumed after sync1)
        if (tid < BC * INk) {
            int b = tid >> 3, i = tid & 7;
            s.x[xp][b][i] = inputs[(size_t)(bg0 + b) * INk * Tk + (size_t)i * Tk + (st + 1)];
        }

        // ---- per-warp: wait for slice w of h[st], stage into hbuf ----
        {
            volatile int* fp = &g_flag[bb][w][0];
            while (*fp < st) { }
            __threadfence();              // acquire
            const float4* src = reinterpret_cast<const float4*>(&g_h[par][bb][w][0]);
            #pragma unroll
            for (int i = 0; i < 4; ++i) {
                int q = lane + 32 * i;           // 0..127
                float4 v = src[q];
                *reinterpret_cast<float4*>(&s.hbuf[q >> 4][w * HJ + (q & 15) * 4]) = v;
            }
            __syncwarp();
        }

        // ---- matvec over this warp's K slice (FFMA2, k-paired) ----
        ull acc[4][4];
        #pragma unroll
        for (int i = 0; i < 4; ++i)
            #pragma unroll
            for (int jj = 0; jj < 4; ++jj) acc[i][jj] = 0ull;

        #pragma unroll 4
        for (int q = 0; q < 16; ++q) {
            ulonglong2 hp[4];
            #pragma unroll
            for (int i = 0; i < 4; ++i)
                hp[i] = h2[(b0 + i) * 128 + w * 16 + q];
            #pragma unroll
            for (int t = 0; t < 2; ++t) {
                int k2 = w * 32 + 2 * q + t;
                ulonglong2 wA = w2row[k2 * 32 + jgrp * 2];
                ulonglong2 wB = w2row[k2 * 32 + jgrp * 2 + 1];
                #pragma unroll
                for (int i = 0; i < 4; ++i) {
                    ull hh = (t == 0) ? hp[i].x : hp[i].y;
                    fma2(acc[i][0], wA.x, hh);
                    fma2(acc[i][1], wA.y, hh);
                    fma2(acc[i][2], wB.x, hh);
                    fma2(acc[i][3], wB.y, hh);
                }
            }
        }
        #pragma unroll
        for (int i = 0; i < 4; ++i) {
            float r[4];
            #pragma unroll
            for (int jj = 0; jj < 4; ++jj) {
                F2U u; u.u = acc[i][jj];
                r[jj] = u.f.x + u.f.y;
            }
            *reinterpret_cast<float4*>(&s.red[w][b0 + i][jgrp * 4]) =
                make_float4(r[0], r[1], r[2], r[3]);
        }
        __syncthreads();   // sync1: red, hbuf, x staged

        // ---- finalize h[st+1]; keyCTA also computes key partials from hbuf=h[st] ----
        #pragma unroll
        for (int l = 0; l < 2; ++l) {
            int o = tid + l * NTHR;
            int b = o >> 6, j = o & 63;
            float v = s.bias[j];
            #pragma unroll
            for (int ww = 0; ww < 8; ++ww) v += s.red[ww][b][j];
            #pragma unroll
            for (int i = 0; i < INk; ++i) v = fmaf(s.x[xp][b][i], s.Win[j][i], v);
            float h = tanhf(v);
            g_h[par ^ 1][bb][jb][o] = h;
            s.hist[b][j][(st + 1) & 7] = h;
        }
        if (keyCTA && st >= 1) {
            int p = tid >> 4, kg = tid & 15;
            int b = p >> 1, o = p & 1;
            float acck = 0.f;
            #pragma unroll
            for (int kk = 0; kk < 32; ++kk) {
                int k = kg * 32 + kk;
                acck = fmaf(s.hbuf[b][k], s.Wk[o][k], acck);
            }
            s.kred[p][kg] = acck;
        }
        __syncthreads();   // sync2: h slice fully written, kred ready

        // publish slice (release)
        if (tid == 0) {
            __threadfence();
            g_flag[bb][jb][0] = st + 1;
        }

        // ---- key head + pr (keyCTA, warp0; off producers' critical path) ----
        if (keyCTA) {
            if (st >= 1 && tid < 16) {
                int b2 = tid >> 1, o2 = tid & 1;
                float z = s.bkey[o2];
                #pragma unroll
                for (int g = 0; g < 16; ++g) z += s.kred[tid][g];
                float kv = 1.f / (1.f + expf(-z));
                keysOut[(size_t)(bg0 + b2) * 2 * Tk + (size_t)o2 * Tk + st] = kv;
                if (o2 == 0) s.key0[b2] = kv;   // key[st-1] = key_pre for this step's pr
            }
            __syncwarp(0xffffffffu & ((tid < 32) ? 0xffffffffu : 0xffffffffu)); // full-warp sync in warp0 path below
            if (tid < 32) {
                __syncwarp();
                int b = tid >> 2, c = tid & 3;
                float kp = (st >= 1) ? s.key0[b] : 1.0f;
                float tm, arm;
                if (c < 2) { tm = s.x[xp][b][6]; arm = s.x[xp][b][c]; }
                else       { tm = s.x[xp][b][7]; arm = s.x[xp][b][c] * kp + s.x[xp][b][c + 2] * (1.f - kp); }
                float d = (tm - arm) / (0.15f * arm);
                float v = (tm == 0.f) ? 0.f : d * d;
                prsOut[(size_t)(bg0 + b) * 4 * Tk + (size_t)c * Tk + (st + 1)] = v;
            }
        }

        // ---- flush 8-step history to hs (same-thread slots; no extra sync needed) ----
        if (((st + 1) & 7) == 7) {
            const int base = st - 6;
            #pragma unroll
            for (int l = 0; l < 2; ++l) {
                int o = tid + l * NTHR;
                int b = o >> 6, j = o & 63;
                float4 lo = *reinterpret_cast<float4*>(&s.hist[b][j][0]);
                float4 hi = *reinterpret_cast<float4*>(&s.hist[b][j][4]);
                float* dst = &hsOut[(size_t)(bg0 + b) * Hk * Tk + (size_t)(jg0 + j) * Tk + base];
                *reinterpret_cast<float4*>(dst)     = lo;
                *reinterpret_cast<float4*>(dst + 4) = hi;
            }
        }
    }

    // ================ epilogue: key[1022] from h[1023] -> keys[:,:,1023] ================
    if (keyCTA) {
        {
            volatile int* fp = &g_flag[bb][w][0];
            while (*fp < STEPS) { }
            __threadfence();
            const float4* src = reinterpret_cast<const float4*>(&g_h[STEPS & 1][bb][w][0]);
            #pragma unroll
            for (int i = 0; i < 4; ++i) {
                int q = lane + 32 * i;
                float4 v = src[q];
                *reinterpret_cast<float4*>(&s.hbuf[q >> 4][w * HJ + (q & 15) * 4]) = v;
            }
        }
        __syncthreads();
        {
            int p = tid >> 4, kg = tid & 15;
            int b = p >> 1, o = p & 1;
            float acck = 0.f;
            #pragma unroll
            for (int kk = 0; kk < 32; ++kk) {
                int k = kg * 32 + kk;
                acck = fmaf(s.hbuf[b][k], s.Wk[o][k], acck);
            }
            s.kred[p][kg] = acck;
        }
        __syncthreads();
        if (tid < 16) {
            int b2 = tid >> 1, o2 = tid & 1;
            float z = s.bkey[o2];
            #pragma unroll
            for (int g = 0; g < 16; ++g) z += s.kred[tid][g];
            float kv = 1.f / (1.f + expf(-z));
            keysOut[(size_t)(bg0 + b2) * 2 * Tk + (size_t)o2 * Tk + (Tk - 1)] = kv;
        }
    }
}

extern "C" void kernel_launch(void* const* d_in, const int* in_sizes, int n_in,
                              void* d_out, int out_size) {
    const float* inputs = (const float*)d_in[0];
    const float* W_in   = (const float*)d_in[1];
    const float* b_in   = (const float*)d_in[2];
    const float* W_rec  = (const float*)d_in[3];
    const float* b_rec  = (const float*)d_in[4];
    const float* W_key  = (const float*)d_in[5];
    const float* b_key  = (const float*)d_in[6];
    float* out = (float*)d_out;

    static bool attr_set = false;
    if (!attr_set) {
        cudaFuncSetAttribute(rnn_flag_kernel,
                             cudaFuncAttributeMaxDynamicSharedMemorySize,
                             (int)sizeof(Smem));
        attr_set = true;
    }
    rnn_flag_kernel<<<NCTA, NTHR, sizeof(Smem)>>>(
        inputs, W_in, b_in, W_rec, b_rec, W_key, b_key, out);
}

// round 4
// speedup vs baseline: 1.1941x; 1.0526x over previous
#include <cuda_runtime.h>
#include <math.h>

#define Bk   128
#define Hk   512
#define Tk   1024
#define INk  8
#define OUTk 2

#define JB   8
#define BBL  16
#define HJ   64      // H / JB
#define BC   8       // B / BBL
#define NCTA 128     // JB * BBL
#define NTHR 512     // 16 warps
#define NW   16
#define KW   32      // K columns per warp
#define STEPS (Tk - 1)

typedef unsigned long long ull;

// ---------------- device globals ----------------
__device__ float g_h[2][BBL][JB][BC * HJ];     // h ping-pong, sliced
__device__ volatile int g_flag[BBL][JB][8];    // flag[bb][jb][0] = latest step published
__device__ unsigned g_count;
__device__ volatile unsigned g_epoch;

// ---------------- shared memory ----------------
struct __align__(16) Smem {
    ull   wt2[Hk / 2][HJ];     // W_rec slice, k-pair packed                128 KB
    float hbuf[BC][Hk];        // staged h_pre                                16 KB
    float red[NW][BC][HJ];     // per-warp K partials                         32 KB
    float hist[BC][HJ][8];     // 8-step h history                            16 KB
    float Win[HJ][INk];
    float bias[HJ];
    float Wk[OUTk][Hk];
    float bkey[OUTk];
    float x[2][BC][INk];
    float key0[BC];
    float kred[16][16];
};

union F2U { ull u; float2 f; };

__device__ __forceinline__ void fma2(ull& d, ull a, ull b) {
    asm("fma.rn.f32x2 %0, %1, %2, %0;" : "+l"(d) : "l"(a), "l"(b));
}

__device__ __forceinline__ int flag_acquire(const int* fp) {
    int v;
    asm volatile("ld.acquire.gpu.global.s32 %0, [%1];" : "=r"(v) : "l"(fp) : "memory");
    return v;
}

__device__ __forceinline__ void init_grid_barrier() {
    __syncthreads();
    if (threadIdx.x == 0) {
        __threadfence();
        unsigned e = g_epoch;
        if (atomicAdd(&g_count, 1u) == NCTA - 1u) {
            atomicExch(&g_count, 0u);
            __threadfence();
            g_epoch = e + 1u;
        } else {
            while (g_epoch == e) { }
            __threadfence();
        }
    }
    __syncthreads();
}

__global__ void __launch_bounds__(NTHR, 1)
rnn_flag_kernel(const float* __restrict__ inputs,   // [B][IN][T]
                const float* __restrict__ W_in,     // [H][IN]
                const float* __restrict__ b_in,
                const float* __restrict__ W_rec,    // [H][H]
                const float* __restrict__ b_rec,
                const float* __restrict__ W_key,    // [OUT][H]
                const float* __restrict__ b_key,
                float* __restrict__ out)
{
    extern __shared__ char smraw[];
    Smem& s = *reinterpret_cast<Smem*>(smraw);

    const int tid = threadIdx.x;
    const int cta = blockIdx.x;
    const int jb  = cta % JB;
    const int bb  = cta / JB;
    const int jg0 = jb * HJ;
    const int bg0 = bb * BC;
    const bool keyCTA = (jb == 0);

    float* keysOut = out;                                             // [B][2][T]
    float* prsOut  = out + (size_t)Bk * 2 * Tk;                       // [B][4][T]
    float* hsOut   = out + (size_t)Bk * 2 * Tk + (size_t)Bk * 4 * Tk; // [B][H][T]

    // ---------------- one-time init ----------------
    {
        const float2* wr2 = reinterpret_cast<const float2*>(W_rec);
        for (int idx = tid; idx < HJ * (Hk / 2); idx += NTHR) {
            int j  = idx >> 8;
            int k2 = idx & 255;
            F2U u; u.f = wr2[(size_t)(jg0 + j) * (Hk / 2) + k2];
            s.wt2[k2][j] = u.u;
        }
    }
    for (int idx = tid; idx < HJ * INk; idx += NTHR) {
        int j = idx / INk, i = idx % INk;
        s.Win[j][i] = W_in[(jg0 + j) * INk + i];
    }
    for (int j = tid; j < HJ; j += NTHR)
        s.bias[j] = b_in[jg0 + j] + b_rec[jg0 + j];
    if (keyCTA) {
        for (int idx = tid; idx < OUTk * Hk; idx += NTHR)
            s.Wk[idx / Hk][idx % Hk] = W_key[idx];
        if (tid < OUTk) s.bkey[tid] = b_key[tid];
        if (tid < BC) s.key0[tid] = 1.0f;
        if (tid < BC * 2) {
            int b = tid >> 1, o = tid & 1;
            keysOut[(size_t)(bg0 + b) * 2 * Tk + (size_t)o * Tk + 0] = 0.f;
        }
        if (tid < BC * 4) {
            int b = tid >> 2, c = tid & 3;
            prsOut[(size_t)(bg0 + b) * 4 * Tk + (size_t)c * Tk + 0] = 0.f;
        }
    }
    for (int o = tid; o < BC * HJ; o += NTHR)
        g_h[0][bb][jb][o] = 0.f;
    if (tid == 0) g_flag[bb][jb][0] = 0;
    if (tid < BC * HJ) {
        int b = tid >> 6, j = tid & 63;
        s.hist[b][j][0] = 0.f;
    }
    __syncthreads();
    init_grid_barrier();

    const int w    = tid >> 5;
    const int lane = tid & 31;
    const int jgrp = lane & 15;          // j0 = 4*jgrp
    const int b0   = (lane >> 4) * 4;    // 0 or 4
    const int srcSlice = w >> 1;         // producer slice this warp consumes
    const int jhalf = w & 1;             // which 32-j half of that slice

    const ulonglong2* w2row = reinterpret_cast<const ulonglong2*>(&s.wt2[0][0]); // [k2*32 + jpair]
    const ull*        hU    = reinterpret_cast<const ull*>(&s.hbuf[0][0]);       // [b*256 + k2]

    // ================ time loop ================
    for (int st = 0; st < STEPS; ++st) {
        const int par = st & 1;
        const int xp  = st & 1;

        if (tid < BC * INk) {
            int b = tid >> 3, i = tid & 7;
            s.x[xp][b][i] = inputs[(size_t)(bg0 + b) * INk * Tk + (size_t)i * Tk + (st + 1)];
        }

        // ---- per-warp: acquire-poll slice flag, stage own 32-k half via L2 ----
        {
            const int* fp = (const int*)&g_flag[bb][srcSlice][0];
            while (flag_acquire(fp) < st) { }
            const float4* src = reinterpret_cast<const float4*>(&g_h[par][bb][srcSlice][0]);
            #pragma unroll
            for (int i = 0; i < 2; ++i) {
                int e = lane + 32 * i;       // 0..63
                int b = e >> 3, kq = e & 7;
                float4 v = __ldcg(&src[b * 16 + jhalf * 8 + kq]);
                *reinterpret_cast<float4*>(&s.hbuf[b][w * KW + kq * 4]) = v;
            }
            __syncwarp();
        }

        // ---- matvec over this warp's 32-k slice (FFMA2) ----
        ull acc[4][4];
        #pragma unroll
        for (int i = 0; i < 4; ++i)
            #pragma unroll
            for (int jj = 0; jj < 4; ++jj) acc[i][jj] = 0ull;

        #pragma unroll
        for (int kk2 = 0; kk2 < 16; ++kk2) {
            const int k2 = w * 16 + kk2;
            ulonglong2 wA = w2row[k2 * 32 + jgrp * 2];
            ulonglong2 wB = w2row[k2 * 32 + jgrp * 2 + 1];
            #pragma unroll
            for (int i = 0; i < 4; ++i) {
                ull hh = hU[(b0 + i) * 256 + k2];
                fma2(acc[i][0], wA.x, hh);
                fma2(acc[i][1], wA.y, hh);
                fma2(acc[i][2], wB.x, hh);
                fma2(acc[i][3], wB.y, hh);
            }
        }
        #pragma unroll
        for (int i = 0; i < 4; ++i) {
            float r[4];
            #pragma unroll
            for (int jj = 0; jj < 4; ++jj) {
                F2U u; u.u = acc[i][jj];
                r[jj] = u.f.x + u.f.y;
            }
            *reinterpret_cast<float4*>(&s.red[w][b0 + i][jgrp * 4]) =
                make_float4(r[0], r[1], r[2], r[3]);
        }
        __syncthreads();   // sync1: red, hbuf, x staged

        // ---- finalize h[st+1]; keyCTA computes key partials from hbuf = h[st] ----
        {
            int b = tid >> 6, j = tid & 63;
            float v = s.bias[j];
            #pragma unroll
            for (int ww = 0; ww < NW; ++ww) v += s.red[ww][b][j];
            #pragma unroll
            for (int i = 0; i < INk; ++i) v = fmaf(s.x[xp][b][i], s.Win[j][i], v);
            float h = tanhf(v);
            g_h[par ^ 1][bb][jb][tid] = h;
            s.hist[b][j][(st + 1) & 7] = h;
        }
        if (keyCTA && st >= 1 && tid < 256) {
            int p = tid >> 4, kg = tid & 15;
            int b = p >> 1, o = p & 1;
            float acck = 0.f;
            #pragma unroll
            for (int kk = 0; kk < 32; ++kk) {
                int k = kg * 32 + kk;
                acck = fmaf(s.hbuf[b][k], s.Wk[o][k], acck);
            }
            s.kred[p][kg] = acck;
        }
        __syncthreads();   // sync2: h slice fully written, kred ready

        // publish slice (single fence per CTA-step)
        if (tid == 0) {
            __threadfence();
            g_flag[bb][jb][0] = st + 1;
        }

        // ---- key head + pr (keyCTA; off producers' critical path) ----
        if (keyCTA) {
            if (st >= 1 && tid < 16) {
                int b2 = tid >> 1, o2 = tid & 1;
                float z = s.bkey[o2];
                #pragma unroll
                for (int g = 0; g < 16; ++g) z += s.kred[tid][g];
                float kv = 1.f / (1.f + expf(-z));
                keysOut[(size_t)(bg0 + b2) * 2 * Tk + (size_t)o2 * Tk + st] = kv;
                if (o2 == 0) s.key0[b2] = kv;
            }
            if (tid < 32) {
                __syncwarp();
                int b = tid >> 2, c = tid & 3;
                float kp = (st >= 1) ? s.key0[b] : 1.0f;
                float tm, arm;
                if (c < 2) { tm = s.x[xp][b][6]; arm = s.x[xp][b][c]; }
                else       { tm = s.x[xp][b][7]; arm = s.x[xp][b][c] * kp + s.x[xp][b][c + 2] * (1.f - kp); }
                float d = (tm - arm) / (0.15f * arm);
                float v = (tm == 0.f) ? 0.f : d * d;
                prsOut[(size_t)(bg0 + b) * 4 * Tk + (size_t)c * Tk + (st + 1)] = v;
            }
        }

        // ---- flush 8-step history (same-thread slots, no extra sync) ----
        if (((st + 1) & 7) == 7) {
            const int base = st - 6;
            int b = tid >> 6, j = tid & 63;
            float4 lo = *reinterpret_cast<float4*>(&s.hist[b][j][0]);
            float4 hi = *reinterpret_cast<float4*>(&s.hist[b][j][4]);
            float* dst = &hsOut[(size_t)(bg0 + b) * Hk * Tk + (size_t)(jg0 + j) * Tk + base];
            *reinterpret_cast<float4*>(dst)     = lo;
            *reinterpret_cast<float4*>(dst + 4) = hi;
        }
    }

    // ================ epilogue: key[1022] from h[1023] -> keys[:,:,1023] ================
    if (keyCTA) {
        {
            const int* fp = (const int*)&g_flag[bb][srcSlice][0];
            while (flag_acquire(fp) < STEPS) { }
            const float4* src = reinterpret_cast<const float4*>(&g_h[STEPS & 1][bb][srcSlice][0]);
            #pragma unroll
            for (int i = 0; i < 2; ++i) {
                int e = lane + 32 * i;
                int b = e >> 3, kq = e & 7;
                float4 v = __ldcg(&src[b * 16 + jhalf * 8 + kq]);
                *reinterpret_cast<float4*>(&s.hbuf[b][w * KW + kq * 4]) = v;
            }
        }
        __syncthreads();
        if (tid < 256) {
            int p = tid >> 4, kg = tid & 15;
            int b = p >> 1, o = p & 1;
            float acck = 0.f;
            #pragma unroll
            for (int kk = 0; kk < 32; ++kk) {
                int k = kg * 32 + kk;
                acck = fmaf(s.hbuf[b][k], s.Wk[o][k], acck);
            }
            s.kred[p][kg] = acck;
        }
        __syncthreads();
        if (tid < 16) {
            int b2 = tid >> 1, o2 = tid & 1;
            float z = s.bkey[o2];
            #pragma unroll
            for (int g = 0; g < 16; ++g) z += s.kred[tid][g];
            float kv = 1.f / (1.f + expf(-z));
            keysOut[(size_t)(bg0 + b2) * 2 * Tk + (size_t)o2 * Tk + (Tk - 1)] = kv;
        }
    }
}

extern "C" void kernel_launch(void* const* d_in, const int* in_sizes, int n_in,
                              void* d_out, int out_size) {
    const float* inputs = (const float*)d_in[0];
    const float* W_in   = (const float*)d_in[1];
    const float* b_in   = (const float*)d_in[2];
    const float* W_rec  = (const float*)d_in[3];
    const float* b_rec  = (const float*)d_in[4];
    const float* W_key  = (const float*)d_in[5];
    const float* b_key  = (const float*)d_in[6];
    float* out = (float*)d_out;

    static bool attr_set = false;
    if (!attr_set) {
        cudaFuncSetAttribute(rnn_flag_kernel,
                             cudaFuncAttributeMaxDynamicSharedMemorySize,
                             (int)sizeof(Smem));
        attr_set = true;
    }
    rnn_flag_kernel<<<NCTA, NTHR, sizeof(Smem)>>>(
        inputs, W_in, b_in, W_rec, b_rec, W_key, b_key, out);
}